// round 1
// baseline (speedup 1.0000x reference)
#include <cuda_runtime.h>
#include <math.h>

#define MAXN 50000
#define FDIM 128
#define TM   64
#define LDA  132
#define NTHR 256
#define PLANE ((size_t)MAXN * FDIM)

// -------- scratch (allocation-free: __device__ globals) --------
__device__ float g_M0[MAXN * FDIM];
__device__ float g_M1[3][MAXN * FDIM];
__device__ float g_M2[3][MAXN * FDIM];
__device__ float g_M3[3][MAXN * FDIM];
__device__ float g_ms[MAXN * FDIM];
__device__ float g_mv[3][MAXN * FDIM];

// -------- shared GEMM core: C[64x128] = A[64x128] @ B[128x128] --------
// As padded lda=132; Bs row-major [128][128]. 256 threads, micro-tile 8x4.
__device__ __forceinline__ void gemm_tile(const float* __restrict__ As,
                                          const float* __restrict__ Bs,
                                          float acc[8][4], int trow, int tcol) {
    const float* a = As + trow * 8 * LDA;
    const float* b = Bs + tcol * 4;
#pragma unroll 4
    for (int k = 0; k < FDIM; k += 2) {
        float4 b0 = *(const float4*)(b + (size_t)k * FDIM);
        float4 b1 = *(const float4*)(b + (size_t)(k + 1) * FDIM);
#pragma unroll
        for (int i = 0; i < 8; ++i) {
            float2 av = *(const float2*)(a + i * LDA + k);
            acc[i][0] += av.x * b0.x; acc[i][1] += av.x * b0.y;
            acc[i][2] += av.x * b0.z; acc[i][3] += av.x * b0.w;
            acc[i][0] += av.y * b1.x; acc[i][1] += av.y * b1.y;
            acc[i][2] += av.y * b1.z; acc[i][3] += av.y * b1.w;
        }
    }
}

__device__ __forceinline__ void zero_acc(float acc[8][4]) {
#pragma unroll
    for (int i = 0; i < 8; ++i)
#pragma unroll
        for (int j = 0; j < 4; ++j) acc[i][j] = 0.f;
}

__device__ __forceinline__ void load_A_rm(float* As, const float* __restrict__ src,
                                          int n0, int N) {
    for (int i = threadIdx.x; i < TM * 32; i += NTHR) {
        int r = i >> 5;
        int c4 = (i & 31) * 4;
        float4 v = make_float4(0.f, 0.f, 0.f, 0.f);
        if (n0 + r < N) v = *(const float4*)(src + (size_t)(n0 + r) * FDIM + c4);
        *(float4*)(As + r * LDA + c4) = v;
    }
}

__device__ __forceinline__ void load_B(float* Bs, const float* __restrict__ W) {
    for (int i = threadIdx.x; i < FDIM * FDIM / 4; i += NTHR)
        ((float4*)Bs)[i] = ((const float4*)W)[i];
}

// -------- kernel 1/4: out = silu(in @ W1 + b1) @ W2 + b2 --------
__global__ void __launch_bounds__(NTHR) dense2_kernel(
    const float* __restrict__ in, const float* __restrict__ W1, const float* __restrict__ b1,
    const float* __restrict__ W2, const float* __restrict__ b2,
    float* __restrict__ out, int N) {
    extern __shared__ float sm[];
    float* As = sm;
    float* Bs = sm + TM * LDA;
    int n0 = blockIdx.x * TM;
    int trow = threadIdx.x >> 5, tcol = threadIdx.x & 31;

    load_A_rm(As, in, n0, N);
    load_B(Bs, W1);
    __syncthreads();

    float acc[8][4];
    zero_acc(acc);
    gemm_tile(As, Bs, acc, trow, tcol);
    __syncthreads();  // all reads of As/Bs done

    float bb[4];
#pragma unroll
    for (int j = 0; j < 4; ++j) bb[j] = b1[tcol * 4 + j];
#pragma unroll
    for (int i = 0; i < 8; ++i)
#pragma unroll
        for (int j = 0; j < 4; ++j) {
            float x = acc[i][j] + bb[j];
            As[(trow * 8 + i) * LDA + tcol * 4 + j] = x / (1.f + __expf(-x));
        }
    load_B(Bs, W2);
    __syncthreads();

    float acc2[8][4];
    zero_acc(acc2);
    gemm_tile(As, Bs, acc2, trow, tcol);

    float b2v[4];
#pragma unroll
    for (int j = 0; j < 4; ++j) b2v[j] = b2[tcol * 4 + j];
#pragma unroll
    for (int i = 0; i < 8; ++i) {
        int n = n0 + trow * 8 + i;
        if (n < N) {
            *(float4*)(out + (size_t)n * FDIM + tcol * 4) =
                make_float4(acc2[i][0] + b2v[0], acc2[i][1] + b2v[1],
                            acc2[i][2] + b2v[2], acc2[i][3] + b2v[3]);
        }
    }
}

// -------- kernel 2: M{1,2,3}[c] = mu[:,:,c] @ WT{1,2,3}  (planar outputs) --------
__global__ void __launch_bounds__(NTHR) muproj_kernel(
    const float* __restrict__ mu,
    const float* __restrict__ WT1, const float* __restrict__ WT2, const float* __restrict__ WT3,
    float* __restrict__ M1, float* __restrict__ M2, float* __restrict__ M3, int N) {
    extern __shared__ float sm[];
    float* As = sm;                 // 3 planes of TM*LDA
    float* Bs = sm + 3 * TM * LDA;
    int n0 = blockIdx.x * TM;
    int trow = threadIdx.x >> 5, tcol = threadIdx.x & 31;

    // de-interleave mu tile (contiguous [TM][128][3]) into 3 padded planes
    for (int i = threadIdx.x * 4; i < TM * FDIM * 3; i += NTHR * 4) {
        int r = i / (FDIM * 3);
        float4 v = make_float4(0.f, 0.f, 0.f, 0.f);
        if (n0 + r < N) v = *(const float4*)(mu + (size_t)n0 * FDIM * 3 + i);
        int rem = i - r * (FDIM * 3);
        float vv[4] = {v.x, v.y, v.z, v.w};
#pragma unroll
        for (int t = 0; t < 4; ++t) {
            int e = rem + t;
            int f = e / 3;
            int c = e - 3 * f;
            As[c * (TM * LDA) + r * LDA + f] = vv[t];
        }
    }

    const float* Ws[3] = {WT1, WT2, WT3};
    float* Ms[3] = {M1, M2, M3};
#pragma unroll
    for (int w = 0; w < 3; ++w) {
        __syncthreads();            // prior reads of Bs (and initial As writes) done
        load_B(Bs, Ws[w]);
        __syncthreads();
#pragma unroll
        for (int c = 0; c < 3; ++c) {
            float acc[8][4];
            zero_acc(acc);
            gemm_tile(As + c * (TM * LDA), Bs, acc, trow, tcol);
            float* dst = Ms[w] + (size_t)c * PLANE;
#pragma unroll
            for (int i = 0; i < 8; ++i) {
                int n = n0 + trow * 8 + i;
                if (n < N) {
                    *(float4*)(dst + (size_t)n * FDIM + tcol * 4) =
                        make_float4(acc[i][0], acc[i][1], acc[i][2], acc[i][3]);
                }
            }
        }
    }
}

// -------- kernel 3: rank-3 tensor contractions -> ms, mv (planar) --------
__global__ void __launch_bounds__(FDIM) combine_kernel(
    const float* __restrict__ T0, const float* __restrict__ T1,
    const float* __restrict__ T2, const float* __restrict__ T3,
    const float* __restrict__ M0, const float* __restrict__ M1,
    const float* __restrict__ M2, const float* __restrict__ M3,
    float* __restrict__ ms, float* __restrict__ mv, int N) {
    int n = blockIdx.x;
    __shared__ float st[40];  // t0, t1[3], t2[9], t3[27]
    int tid = threadIdx.x;
    if (tid == 0) st[0] = T0[n];
    if (tid < 3) st[1 + tid] = T1[(size_t)n * 3 + tid];
    if (tid >= 32 && tid < 41) st[4 + tid - 32] = T2[(size_t)n * 9 + (tid - 32)];
    if (tid >= 64 && tid < 91) st[13 + tid - 64] = T3[(size_t)n * 27 + (tid - 64)];
    __syncthreads();

    float t0 = st[0];
    float t1[3], t2[9], t3[27];
#pragma unroll
    for (int k = 0; k < 3; ++k) t1[k] = st[1 + k];
#pragma unroll
    for (int k = 0; k < 9; ++k) t2[k] = st[4 + k];
#pragma unroll
    for (int k = 0; k < 27; ++k) t3[k] = st[13 + k];

    size_t base = (size_t)n * FDIM + tid;
    float m0 = M0[base];
    float m1[3], m2[3], m3[3];
#pragma unroll
    for (int c = 0; c < 3; ++c) {
        m1[c] = M1[base + (size_t)c * PLANE];
        m2[c] = M2[base + (size_t)c * PLANE];
        m3[c] = M3[base + (size_t)c * PLANE];
    }

    float s = t0 * m0;
#pragma unroll
    for (int i = 0; i < 3; ++i) s += m1[i] * t1[i];
#pragma unroll
    for (int i = 0; i < 3; ++i)
#pragma unroll
        for (int j = 0; j < 3; ++j) s += m2[i] * m2[j] * t2[i * 3 + j];
#pragma unroll
    for (int i = 0; i < 3; ++i) {
        float mi = m3[i];
#pragma unroll
        for (int j = 0; j < 3; ++j) {
            float mij = mi * m3[j];
#pragma unroll
            for (int k = 0; k < 3; ++k) s += mij * m3[k] * t3[i * 9 + j * 3 + k];
        }
    }
    ms[base] = s;

#pragma unroll
    for (int i = 0; i < 3; ++i) {
        float v = t1[i] * m0;
#pragma unroll
        for (int j = 0; j < 3; ++j) v += t2[i * 3 + j] * m1[j];
#pragma unroll
        for (int j = 0; j < 3; ++j)
#pragma unroll
            for (int k = 0; k < 3; ++k) v += t3[i * 9 + j * 3 + k] * m2[j] * m2[k];
        mv[base + (size_t)i * PLANE] = v;
    }
}

// -------- kernel 5: mv_out[n,a,c] = sum_f mv[c][n,f] * Wv[f,a] --------
__global__ void __launch_bounds__(NTHR) vproj_kernel(
    const float* __restrict__ mv, const float* __restrict__ Wv,
    float* __restrict__ out, int N) {
    extern __shared__ float sm[];
    float* As = sm;
    float* Bs = sm + TM * LDA;
    int n0 = blockIdx.x * TM;
    int trow = threadIdx.x >> 5, tcol = threadIdx.x & 31;

    load_B(Bs, Wv);
#pragma unroll
    for (int c = 0; c < 3; ++c) {
        __syncthreads();  // prior gemm reads of As done (and B load visible on c==0)
        load_A_rm(As, mv + (size_t)c * PLANE, n0, N);
        __syncthreads();
        float acc[8][4];
        zero_acc(acc);
        gemm_tile(As, Bs, acc, trow, tcol);
#pragma unroll
        for (int i = 0; i < 8; ++i) {
            int n = n0 + trow * 8 + i;
            if (n < N) {
#pragma unroll
                for (int j = 0; j < 4; ++j)
                    out[(size_t)n * FDIM * 3 + (size_t)(tcol * 4 + j) * 3 + c] = acc[i][j];
            }
        }
    }
}

// -------- launch --------
extern "C" void kernel_launch(void* const* d_in, const int* in_sizes, int n_in,
                              void* d_out, int out_size) {
    const float* feat = (const float*)d_in[0];
    const float* mu   = (const float*)d_in[1];
    const float* T0   = (const float*)d_in[2];
    const float* T1   = (const float*)d_in[3];
    const float* T2   = (const float*)d_in[4];
    const float* T3   = (const float*)d_in[5];
    const float* Wq1  = (const float*)d_in[6];
    const float* bq1  = (const float*)d_in[7];
    const float* Wq2  = (const float*)d_in[8];
    const float* bq2  = (const float*)d_in[9];
    const float* WT1  = (const float*)d_in[10];
    const float* WT2  = (const float*)d_in[11];
    const float* WT3  = (const float*)d_in[12];
    const float* Ws1  = (const float*)d_in[13];
    const float* bs1  = (const float*)d_in[14];
    const float* Ws2  = (const float*)d_in[15];
    const float* bs2  = (const float*)d_in[16];
    const float* Wv   = (const float*)d_in[17];

    int N = in_sizes[0] / FDIM;
    if (N > MAXN) N = MAXN;

    float* out = (float*)d_out;
    float* ms_out = out;                       // [N, 128]
    float* mv_out = out + (size_t)N * FDIM;    // [N, 128, 3]

    size_t smA = (size_t)(TM * LDA + FDIM * FDIM) * sizeof(float);      // ~97 KB
    size_t smB = (size_t)(3 * TM * LDA + FDIM * FDIM) * sizeof(float);  // ~163 KB
    cudaFuncSetAttribute(dense2_kernel, cudaFuncAttributeMaxDynamicSharedMemorySize, (int)smA);
    cudaFuncSetAttribute(muproj_kernel, cudaFuncAttributeMaxDynamicSharedMemorySize, (int)smB);
    cudaFuncSetAttribute(vproj_kernel,  cudaFuncAttributeMaxDynamicSharedMemorySize, (int)smA);

    float *pM0, *pM1, *pM2, *pM3, *pms, *pmv;
    cudaGetSymbolAddress((void**)&pM0, g_M0);
    cudaGetSymbolAddress((void**)&pM1, g_M1);
    cudaGetSymbolAddress((void**)&pM2, g_M2);
    cudaGetSymbolAddress((void**)&pM3, g_M3);
    cudaGetSymbolAddress((void**)&pms, g_ms);
    cudaGetSymbolAddress((void**)&pmv, g_mv);

    int nb = (N + TM - 1) / TM;

    dense2_kernel<<<nb, NTHR, smA>>>(feat, Wq1, bq1, Wq2, bq2, pM0, N);
    muproj_kernel<<<nb, NTHR, smB>>>(mu, WT1, WT2, WT3, pM1, pM2, pM3, N);
    combine_kernel<<<N, FDIM>>>(T0, T1, T2, T3, pM0, pM1, pM2, pM3, pms, pmv, N);
    dense2_kernel<<<nb, NTHR, smA>>>(pms, Ws1, bs1, Ws2, bs2, ms_out, N);
    vproj_kernel<<<nb, NTHR, smA>>>(pmv, Wv, mv_out, N);
}